// round 14
// baseline (speedup 1.0000x reference)
#include <cuda_runtime.h>
#include <cuda_fp16.h>
#include <stdint.h>

#define S_LEN  512
#define BATCH  32
#define NSPAN  131072
#define MROWS  16384   // S*B
#define KDIM   1024
#define NDIM   512

#define BM 64
#define BN 128
#define BK 64                     // fp16 elems per K-chunk
#define NSTG 3
#define NIT  (KDIM/BK)            // 16
#define LDSB 72                   // smem row stride in fp16 (64 + 8 pad) = 144 B
#define A_STG_BYTES (BM*LDSB*2)   // 9216
#define B_STG_BYTES (BN*LDSB*2)   // 18432
#define GEMM_SMEM (NSTG*(A_STG_BYTES+B_STG_BYTES))   // 82944 -> 2 CTAs/SM

#define SPW 16   // spans per warp in span_kernel
#define SPAN_BLOCKS (NSPAN / (8 * SPW))   // 1024

// ---- scratch (static device globals; no runtime allocation) ----
__device__ __align__(256) __half g_A[(size_t)MROWS*KDIM];  // 32 MB
__device__ __align__(256) __half g_W[(size_t)NDIM*KDIM];   //  1 MB
__device__ __align__(256) __half g_P[(size_t)MROWS*NDIM];  // 16 MB
__device__ float g_part[SPAN_BLOCKS*3];
__device__ unsigned g_ctr;

// convert + pack one 16-col group of one A row
__device__ __forceinline__ void convA16(unsigned m, unsigned col,
                                        const float* __restrict__ hidden){
  unsigned r = m >> 5, b = m & 31u;
  uint4 o0 = make_uint4(0u,0u,0u,0u), o1 = o0;
  bool zero = (col < 512u) && (r == 0u);
  if (!zero){
    const float* src = (col < 512u)
        ? hidden + ((size_t)(r-1u)*32u + b)*1024u + col
        : hidden + ((size_t)r*32u + b)*1024u + col;
    float4 v0 = *reinterpret_cast<const float4*>(src);
    float4 v1 = *reinterpret_cast<const float4*>(src+4);
    float4 v2 = *reinterpret_cast<const float4*>(src+8);
    float4 v3 = *reinterpret_cast<const float4*>(src+12);
    __half2 t;
    t = __floats2half2_rn(v0.x, v0.y); o0.x = *reinterpret_cast<uint32_t*>(&t);
    t = __floats2half2_rn(v0.z, v0.w); o0.y = *reinterpret_cast<uint32_t*>(&t);
    t = __floats2half2_rn(v1.x, v1.y); o0.z = *reinterpret_cast<uint32_t*>(&t);
    t = __floats2half2_rn(v1.z, v1.w); o0.w = *reinterpret_cast<uint32_t*>(&t);
    t = __floats2half2_rn(v2.x, v2.y); o1.x = *reinterpret_cast<uint32_t*>(&t);
    t = __floats2half2_rn(v2.z, v2.w); o1.y = *reinterpret_cast<uint32_t*>(&t);
    t = __floats2half2_rn(v3.x, v3.y); o1.z = *reinterpret_cast<uint32_t*>(&t);
    t = __floats2half2_rn(v3.z, v3.w); o1.w = *reinterpret_cast<uint32_t*>(&t);
  }
  uint4* dst = reinterpret_cast<uint4*>(g_A + (size_t)m*1024u + col);
  dst[0] = o0; dst[1] = o1;
}

// ------- combined conversion: A2 fp16 (blocks 0..2047, 2 rows/thread) + W' transpose (2048..2175) -------
__global__ __launch_bounds__(256) void conv_kernel(const float* __restrict__ hidden,
                                                   const float* __restrict__ W1){
  __shared__ float s[64][65];
  if (blockIdx.x < 2048u){
    unsigned idx = blockIdx.x*256u + threadIdx.x;   // 8192*64
    unsigned c16 = idx & 63u;        // 16-col group (never straddles the 512 split)
    unsigned mh  = idx >> 6;         // 0..8191
    unsigned col = c16 * 16u;
    convA16(mh,        col, hidden);
    convA16(mh + 8192, col, hidden);
  } else {
    // tiled transpose of one 64x64 fp32 tile of W1 -> fp16 W'[n][k]
    unsigned bidx = blockIdx.x - 2048u;        // 0..127 = 16 k-tiles x 8 n-tiles
    const int k0 = (bidx & 15) * 64;
    const int n0 = (bidx >> 4) * 64;
    const int t  = threadIdx.x;
    const float sgn = (k0 >= 512) ? -1.f : 1.f;
    {
      const int kl = t >> 4;          // 0..15 (+16*i)
      const int nl = (t & 15) * 4;
      #pragma unroll
      for (int i = 0; i < 4; i++){
        int kk = kl + i*16;
        float4 v = *reinterpret_cast<const float4*>(W1 + (size_t)(k0+kk)*512 + n0 + nl);
        s[kk][nl+0] = v.x; s[kk][nl+1] = v.y; s[kk][nl+2] = v.z; s[kk][nl+3] = v.w;
      }
    }
    __syncthreads();
    {
      const int nl = t >> 2;          // 0..63
      const int kb = (t & 3) * 16;    // 0,16,32,48
      uint4 o0, o1;
      #pragma unroll
      for (int j = 0; j < 8; j++){
        __half2 p = __floats2half2_rn(sgn * s[kb + 2*j][nl],
                                      sgn * s[kb + 2*j + 1][nl]);
        if (j < 4) (&o0.x)[j]   = *reinterpret_cast<uint32_t*>(&p);
        else       (&o1.x)[j-4] = *reinterpret_cast<uint32_t*>(&p);
      }
      __half* dst = g_W + (size_t)(n0 + nl)*1024 + k0 + kb;
      *reinterpret_cast<uint4*>(dst)     = o0;
      *reinterpret_cast<uint4*>(dst + 8) = o1;
    }
  }
}

// ---------------- mma.sync helpers (fp16 accumulate) ----------------
__device__ __forceinline__ void mma_f16(uint32_t* d, const uint32_t* a, const uint32_t* b){
  asm volatile(
    "mma.sync.aligned.m16n8k16.row.col.f16.f16.f16.f16 "
    "{%0,%1}, {%2,%3,%4,%5}, {%6,%7}, {%0,%1};\n"
    : "+r"(d[0]), "+r"(d[1])
    : "r"(a[0]), "r"(a[1]), "r"(a[2]), "r"(a[3]), "r"(b[0]), "r"(b[1]));
}
__device__ __forceinline__ void ldsm_x4(uint32_t* r, uint32_t addr){
  asm volatile("ldmatrix.sync.aligned.m8n8.x4.shared.b16 {%0,%1,%2,%3}, [%4];\n"
    : "=r"(r[0]), "=r"(r[1]), "=r"(r[2]), "=r"(r[3]) : "r"(addr));
}
__device__ __forceinline__ void cpa16(uint32_t dst, const void* src){
  asm volatile("cp.async.cg.shared.global [%0], [%1], 16;\n" :: "r"(dst), "l"(src));
}
__device__ __forceinline__ void cpa_commit(){
  asm volatile("cp.async.commit_group;\n");
}
__device__ __forceinline__ void cpa_wait1(){
  asm volatile("cp.async.wait_group 1;\n");
}

// -------- 3-stage cp.async fp16 GEMM, BM=64 (1024 CTAs for wave balance) --------
extern __shared__ char dsm[];
__global__ __launch_bounds__(256,2) void gemm_kernel(){
  const int tid  = threadIdx.x;
  const int lane = tid & 31;
  const int w    = tid >> 5;
  const int wm   = w & 1;    // 2 warps along M (32 rows)
  const int wn   = w >> 1;   // 4 warps along N (32 cols)

  const __half* __restrict__ Ag = g_A + (size_t)blockIdx.y*BM*KDIM;
  const __half* __restrict__ Bg = g_W + (size_t)blockIdx.x*BN*KDIM;

  uint32_t sbase = (uint32_t)__cvta_generic_to_shared(dsm);
  uint32_t aS[NSTG], bS[NSTG];
  #pragma unroll
  for (int s=0;s<NSTG;s++){
    aS[s] = sbase + s*A_STG_BYTES;
    bS[s] = sbase + NSTG*A_STG_BYTES + s*B_STG_BYTES;
  }

  // cp.async mapping: A 64 rows x 8 chunks = 512 (2/thr); B 128 x 8 = 1024 (4/thr)
  const int arow = tid >> 3;           // 0..31, rows arow, arow+32
  const int brow = tid >> 3;           // rows brow + 32*i, i<4
  const int cseg = (tid & 7) * 8;      // element offset of 16B chunk

  const int a_row = wm*32 + (lane & 15);
  const int a_chL = (lane >> 4) * 8;
  const int b_row = wn*32 + (lane & 7);
  const int b_chL = ((lane >> 3) & 3) * 8;

  uint32_t acc[2][4][2];   // f16x2 accumulators
  #pragma unroll
  for (int i=0;i<2;i++)
    #pragma unroll
    for (int j=0;j<4;j++){ acc[i][j][0]=0u; acc[i][j][1]=0u; }

  // prologue: stages 0,1
  #pragma unroll
  for (int s=0; s<NSTG-1; s++){
    int k0 = s*BK;
    #pragma unroll
    for (int i=0;i<2;i++){
      int row = arow + i*32;
      cpa16(aS[s] + (uint32_t)(row*LDSB + cseg)*2u, Ag + (size_t)row*KDIM + k0 + cseg);
    }
    #pragma unroll
    for (int i=0;i<4;i++){
      int row = brow + i*32;
      cpa16(bS[s] + (uint32_t)(row*LDSB + cseg)*2u, Bg + (size_t)row*KDIM + k0 + cseg);
    }
    cpa_commit();
  }

  int cs = 0, ls = NSTG-1;
  for (int it = 0; it < NIT; it++){
    cpa_wait1();
    __syncthreads();
    if (it + NSTG - 1 < NIT){
      int k0 = (it + NSTG - 1)*BK;
      #pragma unroll
      for (int i=0;i<2;i++){
        int row = arow + i*32;
        cpa16(aS[ls] + (uint32_t)(row*LDSB + cseg)*2u, Ag + (size_t)row*KDIM + k0 + cseg);
      }
      #pragma unroll
      for (int i=0;i<4;i++){
        int row = brow + i*32;
        cpa16(bS[ls] + (uint32_t)(row*LDSB + cseg)*2u, Bg + (size_t)row*KDIM + k0 + cseg);
      }
    }
    cpa_commit();

    uint32_t aL = aS[cs] + (uint32_t)(a_row*LDSB + a_chL)*2u;
    uint32_t bL = bS[cs] + (uint32_t)(b_row*LDSB + b_chL)*2u;

    #pragma unroll
    for (int kk2=0; kk2<2; kk2++){          // 32-k halves of the 64-k chunk
      uint32_t bf[4][4];
      #pragma unroll
      for (int nt=0; nt<4; nt++)
        ldsm_x4(bf[nt], bL + (uint32_t)(nt*8*LDSB*2) + (uint32_t)(kk2*64));
      #pragma unroll
      for (int kk=0; kk<2; kk++){           // 16-k steps
        uint32_t af[2][4];
        #pragma unroll
        for (int mt=0; mt<2; mt++)
          ldsm_x4(af[mt], aL + (uint32_t)(mt*16*LDSB*2) + (uint32_t)(kk2*64 + kk*32));
        #pragma unroll
        for (int mt=0; mt<2; mt++)
          #pragma unroll
          for (int nt=0; nt<4; nt++)
            mma_f16(acc[mt][nt], af[mt], &bf[nt][kk*2]);
      }
    }
    cs = (cs == NSTG-1) ? 0 : cs+1;
    ls = (ls == NSTG-1) ? 0 : ls+1;
  }

  // epilogue: acc regs already hold packed f16 pairs in P layout
  const int rbase = blockIdx.y*BM + wm*32;
  const int cbase = blockIdx.x*BN + wn*32;
  #pragma unroll
  for (int mt=0; mt<2; mt++){
    int r0 = rbase + mt*16 + (lane >> 2);
    #pragma unroll
    for (int nt=0; nt<4; nt++){
      int cc = cbase + nt*8 + (lane & 3)*2;
      *reinterpret_cast<uint32_t*>(g_P + (size_t)r0*NDIM + cc)     = acc[mt][nt][0];
      *reinterpret_cast<uint32_t*>(g_P + (size_t)(r0+8)*NDIM + cc) = acc[mt][nt][1];
    }
  }
}

// ---------------- span pass: 16 spans/warp, merge-tree reduction ----------------
__device__ __forceinline__ float proc8(uint4 e, uint4 q,
                                        const float* __restrict__ bb,
                                        const float* __restrict__ ww, float acc){
  const uint32_t* pe = &e.x;
  const uint32_t* pq = &q.x;
  #pragma unroll
  for (int i=0;i<4;i++){
    float2 ef = __half22float2(*reinterpret_cast<const __half2*>(&pe[i]));
    float2 qf = __half22float2(*reinterpret_cast<const __half2*>(&pq[i]));
    acc = fmaf(fmaxf(ef.x - qf.x + bb[2*i],   0.f), ww[2*i],   acc);
    acc = fmaf(fmaxf(ef.y - qf.y + bb[2*i+1], 0.f), ww[2*i+1], acc);
  }
  return acc;
}

__device__ __forceinline__ float mrg(float a, float b, int m, int lane){
  float d = (lane & m) ? b : a;
  float e = (lane & m) ? a : b;
  return d + __shfl_xor_sync(0xffffffffu, e, m);
}

__global__ __launch_bounds__(256) void span_kernel(
    const int* __restrict__ bids, const int* __restrict__ begins,
    const int* __restrict__ ends, const int* __restrict__ flags,
    const float* __restrict__ wts, const float* __restrict__ b1,
    const float* __restrict__ W2, const float* __restrict__ b2,
    float* __restrict__ out)
{
  __shared__ float s_red[8][3];
  __shared__ unsigned s_rank;
  const int lane = threadIdx.x & 31;
  const int wrp  = threadIdx.x >> 5;
  const int n0   = (blockIdx.x*8 + wrp)*SPW;

  float b1r[16], w2r[16];
  {
    const float4* B1 = reinterpret_cast<const float4*>(b1);
    const float4* Wv = reinterpret_cast<const float4*>(W2);
    float4 t;
    t = B1[2*lane];    b1r[0]=t.x;  b1r[1]=t.y;  b1r[2]=t.z;  b1r[3]=t.w;
    t = B1[2*lane+1];  b1r[4]=t.x;  b1r[5]=t.y;  b1r[6]=t.z;  b1r[7]=t.w;
    t = B1[2*lane+64]; b1r[8]=t.x;  b1r[9]=t.y;  b1r[10]=t.z; b1r[11]=t.w;
    t = B1[2*lane+65]; b1r[12]=t.x; b1r[13]=t.y; b1r[14]=t.z; b1r[15]=t.w;
    t = Wv[2*lane];    w2r[0]=t.x;  w2r[1]=t.y;  w2r[2]=t.z;  w2r[3]=t.w;
    t = Wv[2*lane+1];  w2r[4]=t.x;  w2r[5]=t.y;  w2r[6]=t.z;  w2r[7]=t.w;
    t = Wv[2*lane+64]; w2r[8]=t.x;  w2r[9]=t.y;  w2r[10]=t.z; w2r[11]=t.w;
    t = Wv[2*lane+65]; w2r[12]=t.x; w2r[13]=t.y; w2r[14]=t.z; w2r[15]=t.w;
  }
  const float b2v = b2[0];

  float acc[SPW];
  #pragma unroll
  for (int s = 0; s < SPW; s++){
    const int n = n0 + s;
    const int ib = bids[n], g = begins[n], e = ends[n];
    const uint4* Pe = reinterpret_cast<const uint4*>(g_P + ((size_t)(e*32+ib))*512u);
    const uint4* Pg = reinterpret_cast<const uint4*>(g_P + ((size_t)(g*32+ib))*512u);
    uint4 e0 = Pe[lane], e1 = Pe[lane+32];
    uint4 q0 = Pg[lane], q1 = Pg[lane+32];
    float a = proc8(e0, q0, b1r,   w2r,   0.f);
    acc[s]  = proc8(e1, q1, b1r+8, w2r+8, a);
  }

  float t1[8];
  #pragma unroll
  for (int i=0;i<8;i++) t1[i] = mrg(acc[2*i], acc[2*i+1], 1, lane);
  float t2[4];
  #pragma unroll
  for (int i=0;i<4;i++) t2[i] = mrg(t1[2*i], t1[2*i+1], 2, lane);
  float t3[2];
  #pragma unroll
  for (int i=0;i<2;i++) t3[i] = mrg(t2[2*i], t2[2*i+1], 4, lane);
  float r = mrg(t3[0], t3[1], 8, lane);
  r += __shfl_xor_sync(0xffffffffu, r, 16);

  float sp = 0.f, sn = 0.f, sc = 0.f;
  if (lane < SPW){
    const int n = n0 + lane;
    float logit = r + b2v;
    float pp = 1.f / (1.f + expf(-logit));
    pp = fminf(fmaxf(pp, 1e-7f), 1.f - 1e-7f);
    int fl = flags[n];
    float wgt = wts[n];
    float bce = (fl == 1) ? -logf(pp) : -logf(1.f - pp);
    sp = (fl == 1) ? wgt*bce : 0.f;
    sn = (fl == 1) ? 0.f : wgt*bce;
    sc = (fl == 1) ? 1.f : 0.f;
  }
  #pragma unroll
  for (int off=16; off>0; off>>=1){
    sp += __shfl_xor_sync(0xffffffffu, sp, off);
    sn += __shfl_xor_sync(0xffffffffu, sn, off);
    sc += __shfl_xor_sync(0xffffffffu, sc, off);
  }
  if (lane == 0){ s_red[wrp][0]=sp; s_red[wrp][1]=sn; s_red[wrp][2]=sc; }
  __syncthreads();
  if (threadIdx.x == 0){
    float a=0.f,b=0.f,c=0.f;
    #pragma unroll
    for (int i=0;i<8;i++){ a+=s_red[i][0]; b+=s_red[i][1]; c+=s_red[i][2]; }
    g_part[blockIdx.x*3+0]=a;
    g_part[blockIdx.x*3+1]=b;
    g_part[blockIdx.x*3+2]=c;
  }

  __threadfence();
  if (threadIdx.x == 0) s_rank = atomicAdd(&g_ctr, 1u);
  __syncthreads();
  if (s_rank == gridDim.x - 1u){
    __threadfence();
    __shared__ float fp[256], fn[256], fc[256];
    int t = threadIdx.x;
    float a=0.f, b=0.f, c=0.f;
    for (int i=t; i<SPAN_BLOCKS; i+=256){
      a += g_part[i*3+0];
      b += g_part[i*3+1];
      c += g_part[i*3+2];
    }
    fp[t]=a; fn[t]=b; fc[t]=c;
    __syncthreads();
    for (int s=128; s>0; s>>=1){
      if (t < s){ fp[t]+=fp[t+s]; fn[t]+=fn[t+s]; fc[t]+=fc[t+s]; }
      __syncthreads();
    }
    if (t==0){
      const float Nf = 131072.f;
      float scale = 2.f*fc[0]/Nf;
      out[0] = (fp[0] + scale*fn[0]) / Nf;
      g_ctr = 0u;
    }
  }
}

// ---------------- launch ----------------
extern "C" void kernel_launch(void* const* d_in, const int* in_sizes, int n_in,
                              void* d_out, int out_size){
  const float* hidden = (const float*)d_in[0];
  const int* bids     = (const int*)d_in[1];
  const int* begins   = (const int*)d_in[2];
  const int* ends     = (const int*)d_in[3];
  const int* flags    = (const int*)d_in[4];
  const float* wts    = (const float*)d_in[5];
  const float* W1     = (const float*)d_in[6];
  const float* b1     = (const float*)d_in[7];
  const float* W2     = (const float*)d_in[8];
  const float* b2     = (const float*)d_in[9];

  static bool attr_set = false;
  if (!attr_set){
    cudaFuncSetAttribute(gemm_kernel,
                         cudaFuncAttributeMaxDynamicSharedMemorySize, GEMM_SMEM);
    attr_set = true;
  }

  conv_kernel<<<2176, 256>>>(hidden, W1);
  gemm_kernel<<<dim3(NDIM/BN, MROWS/BM), 256, GEMM_SMEM>>>();
  span_kernel<<<SPAN_BLOCKS, 256>>>(bids, begins, ends, flags, wts, b1, W2, b2,
                                    (float*)d_out);
}

// round 15
// speedup vs baseline: 1.0543x; 1.0543x over previous
#include <cuda_runtime.h>
#include <cuda_fp16.h>
#include <stdint.h>

#define S_LEN  512
#define BATCH  32
#define NSPAN  131072
#define MROWS  16384   // S*B
#define KDIM   1024
#define NDIM   512

#define BM 128
#define BN 128
#define BK 64                     // fp16 elems per K-chunk
#define NSTG 3
#define NIT  (KDIM/BK)            // 16
#define LDSB 72                   // smem row stride in fp16 (64 + 8 pad) = 144 B
#define A_STG_BYTES (BM*LDSB*2)   // 18432
#define B_STG_BYTES (BN*LDSB*2)   // 18432
#define GEMM_SMEM (NSTG*(A_STG_BYTES+B_STG_BYTES))   // 110592 -> 2 CTAs/SM

#define SPW 16   // spans per warp in span_kernel
#define SPAN_BLOCKS (NSPAN / (8 * SPW))   // 1024

// ---- scratch (static device globals; no runtime allocation) ----
__device__ __align__(256) __half g_A[(size_t)MROWS*KDIM];  // 32 MB
__device__ __align__(256) __half g_W[(size_t)NDIM*KDIM];   //  1 MB
__device__ __align__(256) __half g_P[(size_t)MROWS*NDIM];  // 16 MB
__device__ float g_part[SPAN_BLOCKS*3];
__device__ unsigned g_ctr;

// ------- combined conversion: A2 fp16 (blocks 0..4095) + W' tiled transpose (4096..4223) -------
__global__ __launch_bounds__(256) void conv_kernel(const float* __restrict__ hidden,
                                                   const float* __restrict__ W1){
  __shared__ float s[64][65];
  if (blockIdx.x < 4096u){
    unsigned idx = blockIdx.x*256u + threadIdx.x;   // 16384*64
    unsigned c16 = idx & 63u;        // 16-col group (never straddles the 512 split)
    unsigned m   = idx >> 6;         // row 0..16383
    unsigned r   = m >> 5;
    unsigned b   = m & 31u;
    unsigned col = c16 * 16u;
    uint4 o0 = make_uint4(0u,0u,0u,0u), o1 = o0;
    bool zero = (col < 512u) && (r == 0u);
    if (!zero){
      const float* src = (col < 512u)
          ? hidden + ((size_t)(r-1u)*32u + b)*1024u + col
          : hidden + ((size_t)r*32u + b)*1024u + col;
      float4 v0 = *reinterpret_cast<const float4*>(src);
      float4 v1 = *reinterpret_cast<const float4*>(src+4);
      float4 v2 = *reinterpret_cast<const float4*>(src+8);
      float4 v3 = *reinterpret_cast<const float4*>(src+12);
      __half2 t;
      t = __floats2half2_rn(v0.x, v0.y); o0.x = *reinterpret_cast<uint32_t*>(&t);
      t = __floats2half2_rn(v0.z, v0.w); o0.y = *reinterpret_cast<uint32_t*>(&t);
      t = __floats2half2_rn(v1.x, v1.y); o0.z = *reinterpret_cast<uint32_t*>(&t);
      t = __floats2half2_rn(v1.z, v1.w); o0.w = *reinterpret_cast<uint32_t*>(&t);
      t = __floats2half2_rn(v2.x, v2.y); o1.x = *reinterpret_cast<uint32_t*>(&t);
      t = __floats2half2_rn(v2.z, v2.w); o1.y = *reinterpret_cast<uint32_t*>(&t);
      t = __floats2half2_rn(v3.x, v3.y); o1.z = *reinterpret_cast<uint32_t*>(&t);
      t = __floats2half2_rn(v3.z, v3.w); o1.w = *reinterpret_cast<uint32_t*>(&t);
    }
    uint4* dst = reinterpret_cast<uint4*>(g_A + (size_t)m*1024u + col);
    dst[0] = o0; dst[1] = o1;
  } else {
    // tiled transpose of one 64x64 fp32 tile of W1 -> fp16 W'[n][k]
    unsigned bidx = blockIdx.x - 4096u;        // 0..127 = 16 k-tiles x 8 n-tiles
    const int k0 = (bidx & 15) * 64;
    const int n0 = (bidx >> 4) * 64;
    const int t  = threadIdx.x;
    const float sgn = (k0 >= 512) ? -1.f : 1.f;
    {
      const int kl = t >> 4;          // 0..15 (+16*i)
      const int nl = (t & 15) * 4;
      #pragma unroll
      for (int i = 0; i < 4; i++){
        int kk = kl + i*16;
        float4 v = *reinterpret_cast<const float4*>(W1 + (size_t)(k0+kk)*512 + n0 + nl);
        s[kk][nl+0] = v.x; s[kk][nl+1] = v.y; s[kk][nl+2] = v.z; s[kk][nl+3] = v.w;
      }
    }
    __syncthreads();
    {
      const int nl = t >> 2;          // 0..63
      const int kb = (t & 3) * 16;    // 0,16,32,48
      uint4 o0, o1;
      #pragma unroll
      for (int j = 0; j < 8; j++){
        __half2 p = __floats2half2_rn(sgn * s[kb + 2*j][nl],
                                      sgn * s[kb + 2*j + 1][nl]);
        if (j < 4) (&o0.x)[j]   = *reinterpret_cast<uint32_t*>(&p);
        else       (&o1.x)[j-4] = *reinterpret_cast<uint32_t*>(&p);
      }
      __half* dst = g_W + (size_t)(n0 + nl)*1024 + k0 + kb;
      *reinterpret_cast<uint4*>(dst)     = o0;
      *reinterpret_cast<uint4*>(dst + 8) = o1;
    }
  }
}

// ---------------- mma.sync helpers (fp16 accumulate) ----------------
__device__ __forceinline__ void mma_f16(uint32_t* d, const uint32_t* a, const uint32_t* b){
  asm volatile(
    "mma.sync.aligned.m16n8k16.row.col.f16.f16.f16.f16 "
    "{%0,%1}, {%2,%3,%4,%5}, {%6,%7}, {%0,%1};\n"
    : "+r"(d[0]), "+r"(d[1])
    : "r"(a[0]), "r"(a[1]), "r"(a[2]), "r"(a[3]), "r"(b[0]), "r"(b[1]));
}
__device__ __forceinline__ void ldsm_x4(uint32_t* r, uint32_t addr){
  asm volatile("ldmatrix.sync.aligned.m8n8.x4.shared.b16 {%0,%1,%2,%3}, [%4];\n"
    : "=r"(r[0]), "=r"(r[1]), "=r"(r[2]), "=r"(r[3]) : "r"(addr));
}
__device__ __forceinline__ void cpa16(uint32_t dst, const void* src){
  asm volatile("cp.async.cg.shared.global [%0], [%1], 16;\n" :: "r"(dst), "l"(src));
}
__device__ __forceinline__ void cpa_commit(){
  asm volatile("cp.async.commit_group;\n");
}
__device__ __forceinline__ void cpa_wait1(){
  asm volatile("cp.async.wait_group 1;\n");
}

// ---------------- 3-stage cp.async fp16 GEMM, BK=64, 2 CTAs/SM ----------------
extern __shared__ char dsm[];
__global__ __launch_bounds__(256,2) void gemm_kernel(){
  const int tid  = threadIdx.x;
  const int lane = tid & 31;
  const int w    = tid >> 5;
  const int wm   = w & 1;    // 2 warps along M (64 rows)
  const int wn   = w >> 1;   // 4 warps along N (32 cols)

  const __half* __restrict__ Ag = g_A + (size_t)blockIdx.y*BM*KDIM;
  const __half* __restrict__ Bg = g_W + (size_t)blockIdx.x*BN*KDIM;

  uint32_t sbase = (uint32_t)__cvta_generic_to_shared(dsm);
  uint32_t aS[NSTG], bS[NSTG];
  #pragma unroll
  for (int s=0;s<NSTG;s++){
    aS[s] = sbase + s*A_STG_BYTES;
    bS[s] = sbase + NSTG*A_STG_BYTES + s*B_STG_BYTES;
  }

  // cp.async mapping: 128 rows x 8 chunks(16B) = 1024 chunks, 4 per thread
  const int crow = tid >> 3;           // rows: crow + 32*i, i<4
  const int cseg = (tid & 7) * 8;      // element offset of 16B chunk

  const int a_row = wm*64 + (lane & 15);
  const int a_chL = (lane >> 4) * 8;               // elems
  const int b_row = wn*32 + (lane & 7);
  const int b_chL = ((lane >> 3) & 3) * 8;         // elems, covers 32 k per x4

  uint32_t acc[4][4][2];   // f16x2 accumulators
  #pragma unroll
  for (int i=0;i<4;i++)
    #pragma unroll
    for (int j=0;j<4;j++){ acc[i][j][0]=0u; acc[i][j][1]=0u; }

  // prologue: stages 0,1
  #pragma unroll
  for (int s=0; s<NSTG-1; s++){
    int k0 = s*BK;
    #pragma unroll
    for (int i=0;i<4;i++){
      int row = crow + i*32;
      cpa16(aS[s] + (uint32_t)(row*LDSB + cseg)*2u, Ag + (size_t)row*KDIM + k0 + cseg);
      cpa16(bS[s] + (uint32_t)(row*LDSB + cseg)*2u, Bg + (size_t)row*KDIM + k0 + cseg);
    }
    cpa_commit();
  }

  int cs = 0, ls = NSTG-1;
  for (int it = 0; it < NIT; it++){
    cpa_wait1();
    __syncthreads();
    if (it + NSTG - 1 < NIT){
      int k0 = (it + NSTG - 1)*BK;
      #pragma unroll
      for (int i=0;i<4;i++){
        int row = crow + i*32;
        cpa16(aS[ls] + (uint32_t)(row*LDSB + cseg)*2u, Ag + (size_t)row*KDIM + k0 + cseg);
        cpa16(bS[ls] + (uint32_t)(row*LDSB + cseg)*2u, Bg + (size_t)row*KDIM + k0 + cseg);
      }
    }
    cpa_commit();

    uint32_t aL = aS[cs] + (uint32_t)(a_row*LDSB + a_chL)*2u;
    uint32_t bL = bS[cs] + (uint32_t)(b_row*LDSB + b_chL)*2u;

    #pragma unroll
    for (int kk2=0; kk2<2; kk2++){          // 32-k halves of the 64-k chunk
      uint32_t bf[4][4];
      #pragma unroll
      for (int nt=0; nt<4; nt++)
        ldsm_x4(bf[nt], bL + (uint32_t)(nt*8*LDSB*2) + (uint32_t)(kk2*64));
      #pragma unroll
      for (int kk=0; kk<2; kk++){           // 16-k steps
        uint32_t af[4][4];
        #pragma unroll
        for (int mt=0; mt<4; mt++)
          ldsm_x4(af[mt], aL + (uint32_t)(mt*16*LDSB*2) + (uint32_t)(kk2*64 + kk*32));
        #pragma unroll
        for (int mt=0; mt<4; mt++)
          #pragma unroll
          for (int nt=0; nt<4; nt++)
            mma_f16(acc[mt][nt], af[mt], &bf[nt][kk*2]);
      }
    }
    cs = (cs == NSTG-1) ? 0 : cs+1;
    ls = (ls == NSTG-1) ? 0 : ls+1;
  }

  // epilogue: acc regs already hold packed f16 pairs in P layout
  const int rbase = blockIdx.y*BM + wm*64;
  const int cbase = blockIdx.x*BN + wn*32;
  #pragma unroll
  for (int mt=0; mt<4; mt++){
    int r0 = rbase + mt*16 + (lane >> 2);
    #pragma unroll
    for (int nt=0; nt<4; nt++){
      int cc = cbase + nt*8 + (lane & 3)*2;
      *reinterpret_cast<uint32_t*>(g_P + (size_t)r0*NDIM + cc)     = acc[mt][nt][0];
      *reinterpret_cast<uint32_t*>(g_P + (size_t)(r0+8)*NDIM + cc) = acc[mt][nt][1];
    }
  }
}

// ---------------- span pass: 16 spans/warp, merge-tree reduction ----------------
__device__ __forceinline__ float proc8(uint4 e, uint4 q,
                                        const float* __restrict__ bb,
                                        const float* __restrict__ ww, float acc){
  const uint32_t* pe = &e.x;
  const uint32_t* pq = &q.x;
  #pragma unroll
  for (int i=0;i<4;i++){
    float2 ef = __half22float2(*reinterpret_cast<const __half2*>(&pe[i]));
    float2 qf = __half22float2(*reinterpret_cast<const __half2*>(&pq[i]));
    acc = fmaf(fmaxf(ef.x - qf.x + bb[2*i],   0.f), ww[2*i],   acc);
    acc = fmaf(fmaxf(ef.y - qf.y + bb[2*i+1], 0.f), ww[2*i+1], acc);
  }
  return acc;
}

__device__ __forceinline__ float mrg(float a, float b, int m, int lane){
  float d = (lane & m) ? b : a;
  float e = (lane & m) ? a : b;
  return d + __shfl_xor_sync(0xffffffffu, e, m);
}

__global__ __launch_bounds__(256) void span_kernel(
    const int* __restrict__ bids, const int* __restrict__ begins,
    const int* __restrict__ ends, const int* __restrict__ flags,
    const float* __restrict__ wts, const float* __restrict__ b1,
    const float* __restrict__ W2, const float* __restrict__ b2,
    float* __restrict__ out)
{
  __shared__ float s_red[8][3];
  __shared__ unsigned s_rank;
  const int lane = threadIdx.x & 31;
  const int wrp  = threadIdx.x >> 5;
  const int n0   = (blockIdx.x*8 + wrp)*SPW;

  float b1r[16], w2r[16];
  {
    const float4* B1 = reinterpret_cast<const float4*>(b1);
    const float4* Wv = reinterpret_cast<const float4*>(W2);
    float4 t;
    t = B1[2*lane];    b1r[0]=t.x;  b1r[1]=t.y;  b1r[2]=t.z;  b1r[3]=t.w;
    t = B1[2*lane+1];  b1r[4]=t.x;  b1r[5]=t.y;  b1r[6]=t.z;  b1r[7]=t.w;
    t = B1[2*lane+64]; b1r[8]=t.x;  b1r[9]=t.y;  b1r[10]=t.z; b1r[11]=t.w;
    t = B1[2*lane+65]; b1r[12]=t.x; b1r[13]=t.y; b1r[14]=t.z; b1r[15]=t.w;
    t = Wv[2*lane];    w2r[0]=t.x;  w2r[1]=t.y;  w2r[2]=t.z;  w2r[3]=t.w;
    t = Wv[2*lane+1];  w2r[4]=t.x;  w2r[5]=t.y;  w2r[6]=t.z;  w2r[7]=t.w;
    t = Wv[2*lane+64]; w2r[8]=t.x;  w2r[9]=t.y;  w2r[10]=t.z; w2r[11]=t.w;
    t = Wv[2*lane+65]; w2r[12]=t.x; w2r[13]=t.y; w2r[14]=t.z; w2r[15]=t.w;
  }
  const float b2v = b2[0];

  float acc[SPW];
  #pragma unroll
  for (int s = 0; s < SPW; s++){
    const int n = n0 + s;
    const int ib = bids[n], g = begins[n], e = ends[n];
    const uint4* Pe = reinterpret_cast<const uint4*>(g_P + ((size_t)(e*32+ib))*512u);
    const uint4* Pg = reinterpret_cast<const uint4*>(g_P + ((size_t)(g*32+ib))*512u);
    uint4 e0 = Pe[lane], e1 = Pe[lane+32];
    uint4 q0 = Pg[lane], q1 = Pg[lane+32];
    float a = proc8(e0, q0, b1r,   w2r,   0.f);
    acc[s]  = proc8(e1, q1, b1r+8, w2r+8, a);
  }

  float t1[8];
  #pragma unroll
  for (int i=0;i<8;i++) t1[i] = mrg(acc[2*i], acc[2*i+1], 1, lane);
  float t2[4];
  #pragma unroll
  for (int i=0;i<4;i++) t2[i] = mrg(t1[2*i], t1[2*i+1], 2, lane);
  float t3[2];
  #pragma unroll
  for (int i=0;i<2;i++) t3[i] = mrg(t2[2*i], t2[2*i+1], 4, lane);
  float r = mrg(t3[0], t3[1], 8, lane);
  r += __shfl_xor_sync(0xffffffffu, r, 16);

  float sp = 0.f, sn = 0.f, sc = 0.f;
  if (lane < SPW){
    const int n = n0 + lane;
    float logit = r + b2v;
    float pp = 1.f / (1.f + expf(-logit));
    pp = fminf(fmaxf(pp, 1e-7f), 1.f - 1e-7f);
    int fl = flags[n];
    float wgt = wts[n];
    float bce = (fl == 1) ? -logf(pp) : -logf(1.f - pp);
    sp = (fl == 1) ? wgt*bce : 0.f;
    sn = (fl == 1) ? 0.f : wgt*bce;
    sc = (fl == 1) ? 1.f : 0.f;
  }
  #pragma unroll
  for (int off=16; off>0; off>>=1){
    sp += __shfl_xor_sync(0xffffffffu, sp, off);
    sn += __shfl_xor_sync(0xffffffffu, sn, off);
    sc += __shfl_xor_sync(0xffffffffu, sc, off);
  }
  if (lane == 0){ s_red[wrp][0]=sp; s_red[wrp][1]=sn; s_red[wrp][2]=sc; }
  __syncthreads();
  if (threadIdx.x == 0){
    float a=0.f,b=0.f,c=0.f;
    #pragma unroll
    for (int i=0;i<8;i++){ a+=s_red[i][0]; b+=s_red[i][1]; c+=s_red[i][2]; }
    g_part[blockIdx.x*3+0]=a;
    g_part[blockIdx.x*3+1]=b;
    g_part[blockIdx.x*3+2]=c;
  }

  __threadfence();
  if (threadIdx.x == 0) s_rank = atomicAdd(&g_ctr, 1u);
  __syncthreads();
  if (s_rank == gridDim.x - 1u){
    __threadfence();
    __shared__ float fp[256], fn[256], fc[256];
    int t = threadIdx.x;
    float a=0.f, b=0.f, c=0.f;
    for (int i=t; i<SPAN_BLOCKS; i+=256){
      a += g_part[i*3+0];
      b += g_part[i*3+1];
      c += g_part[i*3+2];
    }
    fp[t]=a; fn[t]=b; fc[t]=c;
    __syncthreads();
    for (int s=128; s>0; s>>=1){
      if (t < s){ fp[t]+=fp[t+s]; fn[t]+=fn[t+s]; fc[t]+=fc[t+s]; }
      __syncthreads();
    }
    if (t==0){
      const float Nf = 131072.f;
      float scale = 2.f*fc[0]/Nf;
      out[0] = (fp[0] + scale*fn[0]) / Nf;
      g_ctr = 0u;
    }
  }
}

// ---------------- launch ----------------
extern "C" void kernel_launch(void* const* d_in, const int* in_sizes, int n_in,
                              void* d_out, int out_size){
  const float* hidden = (const float*)d_in[0];
  const int* bids     = (const int*)d_in[1];
  const int* begins   = (const int*)d_in[2];
  const int* ends     = (const int*)d_in[3];
  const int* flags    = (const int*)d_in[4];
  const float* wts    = (const float*)d_in[5];
  const float* W1     = (const float*)d_in[6];
  const float* b1     = (const float*)d_in[7];
  const float* W2     = (const float*)d_in[8];
  const float* b2     = (const float*)d_in[9];

  static bool attr_set = false;
  if (!attr_set){
    cudaFuncSetAttribute(gemm_kernel,
                         cudaFuncAttributeMaxDynamicSharedMemorySize, GEMM_SMEM);
    attr_set = true;
  }

  conv_kernel<<<4224, 256>>>(hidden, W1);
  gemm_kernel<<<dim3(NDIM/BN, MROWS/BM), 256, GEMM_SMEM>>>();
  span_kernel<<<SPAN_BLOCKS, 256>>>(bids, begins, ends, flags, wts, b1, W2, b2,
                                    (float*)d_out);
}

// round 16
// speedup vs baseline: 1.0713x; 1.0161x over previous
#include <cuda_runtime.h>
#include <cuda_fp16.h>
#include <stdint.h>

#define S_LEN  512
#define BATCH  32
#define NSPAN  131072
#define MROWS  16384   // S*B
#define KDIM   1024
#define NDIM   512

#define BM 128
#define BN 128
#define BK 64                     // fp16 elems per K-chunk
#define NSTG 3
#define NIT  (KDIM/BK)            // 16
#define LDSB 72                   // smem row stride in fp16 (64 + 8 pad) = 144 B
#define A_STG_BYTES (BM*LDSB*2)   // 18432
#define B_STG_BYTES (BN*LDSB*2)   // 18432
#define GEMM_SMEM (NSTG*(A_STG_BYTES+B_STG_BYTES))   // 110592 -> 2 CTAs/SM

#define SPW 16   // spans per warp in span_kernel
#define SPAN_BLOCKS (NSPAN / (8 * SPW))   // 1024

// ---- scratch (static device globals; no runtime allocation) ----
__device__ __align__(256) __half g_A[(size_t)MROWS*KDIM];  // 32 MB
__device__ __align__(256) __half g_W[(size_t)NDIM*KDIM];   //  1 MB
__device__ __align__(256) __half g_P[(size_t)MROWS*NDIM];  // 16 MB
__device__ float g_part[SPAN_BLOCKS*3];
__device__ unsigned g_ctr;

// ------- combined conversion: A2 fp16 (blocks 0..4095) + W' tiled transpose (4096..4223) -------
__global__ __launch_bounds__(256) void conv_kernel(const float* __restrict__ hidden,
                                                   const float* __restrict__ W1){
  __shared__ float s[64][65];
  if (blockIdx.x < 4096u){
    unsigned idx = blockIdx.x*256u + threadIdx.x;   // 16384*64
    unsigned c16 = idx & 63u;        // 16-col group (never straddles the 512 split)
    unsigned m   = idx >> 6;         // row 0..16383
    unsigned r   = m >> 5;
    unsigned b   = m & 31u;
    unsigned col = c16 * 16u;
    uint4 o0 = make_uint4(0u,0u,0u,0u), o1 = o0;
    bool zero = (col < 512u) && (r == 0u);
    if (!zero){
      const float* src = (col < 512u)
          ? hidden + ((size_t)(r-1u)*32u + b)*1024u + col
          : hidden + ((size_t)r*32u + b)*1024u + col;
      float4 v0 = *reinterpret_cast<const float4*>(src);
      float4 v1 = *reinterpret_cast<const float4*>(src+4);
      float4 v2 = *reinterpret_cast<const float4*>(src+8);
      float4 v3 = *reinterpret_cast<const float4*>(src+12);
      __half2 t;
      t = __floats2half2_rn(v0.x, v0.y); o0.x = *reinterpret_cast<uint32_t*>(&t);
      t = __floats2half2_rn(v0.z, v0.w); o0.y = *reinterpret_cast<uint32_t*>(&t);
      t = __floats2half2_rn(v1.x, v1.y); o0.z = *reinterpret_cast<uint32_t*>(&t);
      t = __floats2half2_rn(v1.z, v1.w); o0.w = *reinterpret_cast<uint32_t*>(&t);
      t = __floats2half2_rn(v2.x, v2.y); o1.x = *reinterpret_cast<uint32_t*>(&t);
      t = __floats2half2_rn(v2.z, v2.w); o1.y = *reinterpret_cast<uint32_t*>(&t);
      t = __floats2half2_rn(v3.x, v3.y); o1.z = *reinterpret_cast<uint32_t*>(&t);
      t = __floats2half2_rn(v3.z, v3.w); o1.w = *reinterpret_cast<uint32_t*>(&t);
    }
    uint4* dst = reinterpret_cast<uint4*>(g_A + (size_t)m*1024u + col);
    dst[0] = o0; dst[1] = o1;
  } else {
    // tiled transpose of one 64x64 fp32 tile of W1 -> fp16 W'[n][k]
    unsigned bidx = blockIdx.x - 4096u;        // 0..127 = 16 k-tiles x 8 n-tiles
    const int k0 = (bidx & 15) * 64;
    const int n0 = (bidx >> 4) * 64;
    const int t  = threadIdx.x;
    const float sgn = (k0 >= 512) ? -1.f : 1.f;
    {
      const int kl = t >> 4;          // 0..15 (+16*i)
      const int nl = (t & 15) * 4;
      #pragma unroll
      for (int i = 0; i < 4; i++){
        int kk = kl + i*16;
        float4 v = *reinterpret_cast<const float4*>(W1 + (size_t)(k0+kk)*512 + n0 + nl);
        s[kk][nl+0] = v.x; s[kk][nl+1] = v.y; s[kk][nl+2] = v.z; s[kk][nl+3] = v.w;
      }
    }
    __syncthreads();
    {
      const int nl = t >> 2;          // 0..63
      const int kb = (t & 3) * 16;    // 0,16,32,48
      uint4 o0, o1;
      #pragma unroll
      for (int j = 0; j < 8; j++){
        __half2 p = __floats2half2_rn(sgn * s[kb + 2*j][nl],
                                      sgn * s[kb + 2*j + 1][nl]);
        if (j < 4) (&o0.x)[j]   = *reinterpret_cast<uint32_t*>(&p);
        else       (&o1.x)[j-4] = *reinterpret_cast<uint32_t*>(&p);
      }
      __half* dst = g_W + (size_t)(n0 + nl)*1024 + k0 + kb;
      *reinterpret_cast<uint4*>(dst)     = o0;
      *reinterpret_cast<uint4*>(dst + 8) = o1;
    }
  }
}

// ---------------- mma.sync helpers (fp16 accumulate) ----------------
__device__ __forceinline__ void mma_f16(uint32_t* d, const uint32_t* a, const uint32_t* b){
  asm volatile(
    "mma.sync.aligned.m16n8k16.row.col.f16.f16.f16.f16 "
    "{%0,%1}, {%2,%3,%4,%5}, {%6,%7}, {%0,%1};\n"
    : "+r"(d[0]), "+r"(d[1])
    : "r"(a[0]), "r"(a[1]), "r"(a[2]), "r"(a[3]), "r"(b[0]), "r"(b[1]));
}
__device__ __forceinline__ void ldsm_x4(uint32_t* r, uint32_t addr){
  asm volatile("ldmatrix.sync.aligned.m8n8.x4.shared.b16 {%0,%1,%2,%3}, [%4];\n"
    : "=r"(r[0]), "=r"(r[1]), "=r"(r[2]), "=r"(r[3]) : "r"(addr));
}
__device__ __forceinline__ void cpa16(uint32_t dst, const void* src){
  asm volatile("cp.async.cg.shared.global [%0], [%1], 16;\n" :: "r"(dst), "l"(src));
}
__device__ __forceinline__ void cpa_commit(){
  asm volatile("cp.async.commit_group;\n");
}
__device__ __forceinline__ void cpa_wait1(){
  asm volatile("cp.async.wait_group 1;\n");
}

// ---------------- 3-stage cp.async fp16 GEMM, BK=64, 2 CTAs/SM ----------------
extern __shared__ char dsm[];
__global__ __launch_bounds__(256,2) void gemm_kernel(){
  const int tid  = threadIdx.x;
  const int lane = tid & 31;
  const int w    = tid >> 5;
  const int wm   = w & 1;    // 2 warps along M (64 rows)
  const int wn   = w >> 1;   // 4 warps along N (32 cols)

  const __half* __restrict__ Ag = g_A + (size_t)blockIdx.y*BM*KDIM;
  const __half* __restrict__ Bg = g_W + (size_t)blockIdx.x*BN*KDIM;

  uint32_t sbase = (uint32_t)__cvta_generic_to_shared(dsm);
  uint32_t aS[NSTG], bS[NSTG];
  #pragma unroll
  for (int s=0;s<NSTG;s++){
    aS[s] = sbase + s*A_STG_BYTES;
    bS[s] = sbase + NSTG*A_STG_BYTES + s*B_STG_BYTES;
  }

  // cp.async mapping: 128 rows x 8 chunks(16B) = 1024 chunks, 4 per thread
  const int crow = tid >> 3;           // rows: crow + 32*i, i<4
  const int cseg = (tid & 7) * 8;      // element offset of 16B chunk

  const int a_row = wm*64 + (lane & 15);
  const int a_chL = (lane >> 4) * 8;               // elems
  const int b_row = wn*32 + (lane & 7);
  const int b_chL = ((lane >> 3) & 3) * 8;         // elems, covers 32 k per x4

  uint32_t acc[4][4][2];   // f16x2 accumulators
  #pragma unroll
  for (int i=0;i<4;i++)
    #pragma unroll
    for (int j=0;j<4;j++){ acc[i][j][0]=0u; acc[i][j][1]=0u; }

  // prologue: stages 0,1
  #pragma unroll
  for (int s=0; s<NSTG-1; s++){
    int k0 = s*BK;
    #pragma unroll
    for (int i=0;i<4;i++){
      int row = crow + i*32;
      cpa16(aS[s] + (uint32_t)(row*LDSB + cseg)*2u, Ag + (size_t)row*KDIM + k0 + cseg);
      cpa16(bS[s] + (uint32_t)(row*LDSB + cseg)*2u, Bg + (size_t)row*KDIM + k0 + cseg);
    }
    cpa_commit();
  }

  int cs = 0, ls = NSTG-1;
  for (int it = 0; it < NIT; it++){
    cpa_wait1();
    __syncthreads();
    if (it + NSTG - 1 < NIT){
      int k0 = (it + NSTG - 1)*BK;
      #pragma unroll
      for (int i=0;i<4;i++){
        int row = crow + i*32;
        cpa16(aS[ls] + (uint32_t)(row*LDSB + cseg)*2u, Ag + (size_t)row*KDIM + k0 + cseg);
        cpa16(bS[ls] + (uint32_t)(row*LDSB + cseg)*2u, Bg + (size_t)row*KDIM + k0 + cseg);
      }
    }
    cpa_commit();

    uint32_t aL = aS[cs] + (uint32_t)(a_row*LDSB + a_chL)*2u;
    uint32_t bL = bS[cs] + (uint32_t)(b_row*LDSB + b_chL)*2u;

    #pragma unroll
    for (int kk2=0; kk2<2; kk2++){          // 32-k halves of the 64-k chunk
      uint32_t bf[4][4];
      #pragma unroll
      for (int nt=0; nt<4; nt++)
        ldsm_x4(bf[nt], bL + (uint32_t)(nt*8*LDSB*2) + (uint32_t)(kk2*64));
      #pragma unroll
      for (int kk=0; kk<2; kk++){           // 16-k steps
        uint32_t af[4][4];
        #pragma unroll
        for (int mt=0; mt<4; mt++)
          ldsm_x4(af[mt], aL + (uint32_t)(mt*16*LDSB*2) + (uint32_t)(kk2*64 + kk*32));
        #pragma unroll
        for (int mt=0; mt<4; mt++)
          #pragma unroll
          for (int nt=0; nt<4; nt++)
            mma_f16(acc[mt][nt], af[mt], &bf[nt][kk*2]);
      }
    }
    cs = (cs == NSTG-1) ? 0 : cs+1;
    ls = (ls == NSTG-1) ? 0 : ls+1;
  }

  // epilogue: acc regs already hold packed f16 pairs in P layout
  const int rbase = blockIdx.y*BM + wm*64;
  const int cbase = blockIdx.x*BN + wn*32;
  #pragma unroll
  for (int mt=0; mt<4; mt++){
    int r0 = rbase + mt*16 + (lane >> 2);
    #pragma unroll
    for (int nt=0; nt<4; nt++){
      int cc = cbase + nt*8 + (lane & 3)*2;
      *reinterpret_cast<uint32_t*>(g_P + (size_t)r0*NDIM + cc)     = acc[mt][nt][0];
      *reinterpret_cast<uint32_t*>(g_P + (size_t)(r0+8)*NDIM + cc) = acc[mt][nt][1];
    }
  }
}

// ---------------- span pass: 16 spans/warp, merge-tree reduction ----------------
__device__ __forceinline__ float proc8(uint4 e, uint4 q,
                                        const float* __restrict__ bb,
                                        const float* __restrict__ ww, float acc){
  const uint32_t* pe = &e.x;
  const uint32_t* pq = &q.x;
  #pragma unroll
  for (int i=0;i<4;i++){
    float2 ef = __half22float2(*reinterpret_cast<const __half2*>(&pe[i]));
    float2 qf = __half22float2(*reinterpret_cast<const __half2*>(&pq[i]));
    acc = fmaf(fmaxf(ef.x - qf.x + bb[2*i],   0.f), ww[2*i],   acc);
    acc = fmaf(fmaxf(ef.y - qf.y + bb[2*i+1], 0.f), ww[2*i+1], acc);
  }
  return acc;
}

__device__ __forceinline__ float mrg(float a, float b, int m, int lane){
  float d = (lane & m) ? b : a;
  float e = (lane & m) ? a : b;
  return d + __shfl_xor_sync(0xffffffffu, e, m);
}

__global__ __launch_bounds__(256) void span_kernel(
    const int* __restrict__ bids, const int* __restrict__ begins,
    const int* __restrict__ ends, const int* __restrict__ flags,
    const float* __restrict__ wts, const float* __restrict__ b1,
    const float* __restrict__ W2, const float* __restrict__ b2,
    float* __restrict__ out)
{
  __shared__ float s_red[8][3];
  __shared__ unsigned s_rank;
  const int lane = threadIdx.x & 31;
  const int wrp  = threadIdx.x >> 5;
  const int n0   = (blockIdx.x*8 + wrp)*SPW;

  float b1r[16], w2r[16];
  {
    const float4* B1 = reinterpret_cast<const float4*>(b1);
    const float4* Wv = reinterpret_cast<const float4*>(W2);
    float4 t;
    t = B1[2*lane];    b1r[0]=t.x;  b1r[1]=t.y;  b1r[2]=t.z;  b1r[3]=t.w;
    t = B1[2*lane+1];  b1r[4]=t.x;  b1r[5]=t.y;  b1r[6]=t.z;  b1r[7]=t.w;
    t = B1[2*lane+64]; b1r[8]=t.x;  b1r[9]=t.y;  b1r[10]=t.z; b1r[11]=t.w;
    t = B1[2*lane+65]; b1r[12]=t.x; b1r[13]=t.y; b1r[14]=t.z; b1r[15]=t.w;
    t = Wv[2*lane];    w2r[0]=t.x;  w2r[1]=t.y;  w2r[2]=t.z;  w2r[3]=t.w;
    t = Wv[2*lane+1];  w2r[4]=t.x;  w2r[5]=t.y;  w2r[6]=t.z;  w2r[7]=t.w;
    t = Wv[2*lane+64]; w2r[8]=t.x;  w2r[9]=t.y;  w2r[10]=t.z; w2r[11]=t.w;
    t = Wv[2*lane+65]; w2r[12]=t.x; w2r[13]=t.y; w2r[14]=t.z; w2r[15]=t.w;
  }
  const float b2v = b2[0];

  float acc[SPW];
  #pragma unroll
  for (int s = 0; s < SPW; s++){
    const int n = n0 + s;
    const int ib = bids[n], g = begins[n], e = ends[n];
    const uint4* Pe = reinterpret_cast<const uint4*>(g_P + ((size_t)(e*32+ib))*512u);
    const uint4* Pg = reinterpret_cast<const uint4*>(g_P + ((size_t)(g*32+ib))*512u);
    uint4 e0 = Pe[lane], e1 = Pe[lane+32];
    uint4 q0 = Pg[lane], q1 = Pg[lane+32];
    float a = proc8(e0, q0, b1r,   w2r,   0.f);
    acc[s]  = proc8(e1, q1, b1r+8, w2r+8, a);
  }

  float t1[8];
  #pragma unroll
  for (int i=0;i<8;i++) t1[i] = mrg(acc[2*i], acc[2*i+1], 1, lane);
  float t2[4];
  #pragma unroll
  for (int i=0;i<4;i++) t2[i] = mrg(t1[2*i], t1[2*i+1], 2, lane);
  float t3[2];
  #pragma unroll
  for (int i=0;i<2;i++) t3[i] = mrg(t2[2*i], t2[2*i+1], 4, lane);
  float r = mrg(t3[0], t3[1], 8, lane);
  r += __shfl_xor_sync(0xffffffffu, r, 16);

  float sp = 0.f, sn = 0.f, sc = 0.f;
  if (lane < SPW){
    const int n = n0 + lane;
    float logit = r + b2v;
    float pp = 1.f / (1.f + expf(-logit));
    pp = fminf(fmaxf(pp, 1e-7f), 1.f - 1e-7f);
    int fl = flags[n];
    float wgt = wts[n];
    float bce = (fl == 1) ? -logf(pp) : -logf(1.f - pp);
    sp = (fl == 1) ? wgt*bce : 0.f;
    sn = (fl == 1) ? 0.f : wgt*bce;
    sc = (fl == 1) ? 1.f : 0.f;
  }
  #pragma unroll
  for (int off=16; off>0; off>>=1){
    sp += __shfl_xor_sync(0xffffffffu, sp, off);
    sn += __shfl_xor_sync(0xffffffffu, sn, off);
    sc += __shfl_xor_sync(0xffffffffu, sc, off);
  }
  if (lane == 0){ s_red[wrp][0]=sp; s_red[wrp][1]=sn; s_red[wrp][2]=sc; }
  __syncthreads();

  // thread 0 writes this block's partials, then publishes with a RELEASE atomic.
  // (no __threadfence(): gpu-scope fence emits CCTL.IVALL = full L1D flush per
  //  block; atom.release orders thread-0's prior stores without the flush)
  if (threadIdx.x == 0){
    float a=0.f,b=0.f,c=0.f;
    #pragma unroll
    for (int i=0;i<8;i++){ a+=s_red[i][0]; b+=s_red[i][1]; c+=s_red[i][2]; }
    g_part[blockIdx.x*3+0]=a;
    g_part[blockIdx.x*3+1]=b;
    g_part[blockIdx.x*3+2]=c;
    unsigned rank;
    asm volatile("atom.release.gpu.global.add.u32 %0, [%1], %2;"
                 : "=r"(rank) : "l"(&g_ctr), "r"(1u) : "memory");
    s_rank = rank;
  }
  __syncthreads();

  if (s_rank == gridDim.x - 1u){
    __threadfence();   // acquire side: single block, one L1 flush total
    __shared__ float fp[256], fn[256], fc[256];
    int t = threadIdx.x;
    float a=0.f, b=0.f, c=0.f;
    for (int i=t; i<SPAN_BLOCKS; i+=256){
      a += g_part[i*3+0];
      b += g_part[i*3+1];
      c += g_part[i*3+2];
    }
    fp[t]=a; fn[t]=b; fc[t]=c;
    __syncthreads();
    for (int s=128; s>0; s>>=1){
      if (t < s){ fp[t]+=fp[t+s]; fn[t]+=fn[t+s]; fc[t]+=fc[t+s]; }
      __syncthreads();
    }
    if (t==0){
      const float Nf = 131072.f;
      float scale = 2.f*fc[0]/Nf;
      out[0] = (fp[0] + scale*fn[0]) / Nf;
      g_ctr = 0u;
    }
  }
}

// ---------------- launch ----------------
extern "C" void kernel_launch(void* const* d_in, const int* in_sizes, int n_in,
                              void* d_out, int out_size){
  const float* hidden = (const float*)d_in[0];
  const int* bids     = (const int*)d_in[1];
  const int* begins   = (const int*)d_in[2];
  const int* ends     = (const int*)d_in[3];
  const int* flags    = (const int*)d_in[4];
  const float* wts    = (const float*)d_in[5];
  const float* W1     = (const float*)d_in[6];
  const float* b1     = (const float*)d_in[7];
  const float* W2     = (const float*)d_in[8];
  const float* b2     = (const float*)d_in[9];

  static bool attr_set = false;
  if (!attr_set){
    cudaFuncSetAttribute(gemm_kernel,
                         cudaFuncAttributeMaxDynamicSharedMemorySize, GEMM_SMEM);
    attr_set = true;
  }

  conv_kernel<<<4224, 256>>>(hidden, W1);
  gemm_kernel<<<dim3(NDIM/BN, MROWS/BM), 256, GEMM_SMEM>>>();
  span_kernel<<<SPAN_BLOCKS, 256>>>(bids, begins, ends, flags, wts, b1, W2, b2,
                                    (float*)d_out);
}